// round 6
// baseline (speedup 1.0000x reference)
#include <cuda_runtime.h>
#include <cstdint>

#define B_     8
#define S_     2048
#define N_     4096
#define D_     256
#define SLOTS  (D_ / 4)      // 64 float4 per row
#define BLK    16            // block >= max span extent (width <= 15 -> span <= 16 rows)
#define NBLK   (S_ / BLK)    // 128

// Scratch (fp32 only): block-local inclusive prefix P, and U = P - blockTotal
// (negative suffix sum). Any span needs exactly 2 row reads:
//   sum[low..end] = P[end] - (haveSub ? (cross ? U[low-1] : P[low-1]) : 0)
__device__ float g_P[(size_t)B_ * S_ * D_];   // 16.8 MB
__device__ float g_U[(size_t)B_ * S_ * D_];   // 16.8 MB

// ── K1: per-16-row-block prefix + suffix arrays ──────────────────────────────
// thread = (b, blk, slot); 65536 threads, 512 CTAs of 128.
__global__ __launch_bounds__(128) void k_prep(const float4* __restrict__ seq4)
{
    const int tid  = blockIdx.x * 128 + threadIdx.x;
    const int slot = tid & (SLOTS - 1);
    const int p    = tid >> 6;                  // (b, blk)
    const int blk  = p & (NBLK - 1);
    const int b    = p >> 7;                    // NBLK = 128

    const size_t base = ((size_t)b * S_ + (size_t)blk * BLK) * SLOTS + slot;
    const float4* __restrict__ q = seq4 + base;
    float4* __restrict__ Pp = reinterpret_cast<float4*>(g_P) + base;
    float4* __restrict__ Up = reinterpret_cast<float4*>(g_U) + base;

    float4 s = make_float4(0.f, 0.f, 0.f, 0.f);
#pragma unroll
    for (int r = 0; r < BLK; ++r) {
        const float4 v = __ldg(q + r * SLOTS);
        s.x += v.x; s.y += v.y; s.z += v.z; s.w += v.w;
        Pp[r * SLOTS] = s;                      // inclusive prefix
    }
    // s = block total. Second pass: U = P - total (P rows are L1-resident).
#pragma unroll
    for (int r = 0; r < BLK; ++r) {
        const float4 pv = Pp[r * SLOTS];
        Up[r * SLOTS] = make_float4(pv.x - s.x, pv.y - s.y, pv.z - s.z, pv.w - s.w);
    }
}

// ── K2: spans — one warp per 2 spans (8 independent LDG.128 per thread) ──────
// blockDim 256 = 8 warps -> 16 spans/block; grid = 2048.
__global__ __launch_bounds__(256) void k_spans(
    const int2* __restrict__ spans,     // [B, N]
    float4*     __restrict__ out4)      // [B, N, D/4]
{
    const int warp  = threadIdx.x >> 5;
    const int lane  = threadIdx.x & 31;
    const int span0 = (blockIdx.x * 8 + warp) * 2;

    const float4* __restrict__ P4 = reinterpret_cast<const float4*>(g_P);
    const float4* __restrict__ U4 = reinterpret_cast<const float4*>(g_U);

    // Phase 1: metadata for both spans
    int   endv[2], mv[2];
    const float4* srcHi[2];
    const float4* srcSub[2];
    float subScale[2];

#pragma unroll
    for (int i = 0; i < 2; ++i) {
        const int span = span0 + i;
        const int b    = span >> 12;                 // N_ = 4096
        const int2 se  = __ldg(&spans[span]);
        const int end  = se.y;
        const int m    = min(end - se.x, end);       // mask(w) <=> w <= m
        const int low  = end - m;                    // rows [low, end], count m+1

        const bool haveSub = (low & (BLK - 1)) != 0;
        const bool cross   = (low >> 4) != (end >> 4);
        const int  selRow  = max(low - 1, 0);

        const size_t bb = (size_t)b * S_ * SLOTS;
        endv[i]   = end;
        mv[i]     = m;
        srcHi[i]  = P4 + bb + (size_t)end * SLOTS + lane;
        srcSub[i] = (cross ? U4 : P4) + bb + (size_t)selRow * SLOTS + lane;
        subScale[i] = haveSub ? 1.0f : 0.0f;
    }

    // Phase 2: issue all 8 loads (independent -> deep MLP)
    float4 hi0[2], hi1[2], sb0[2], sb1[2];
#pragma unroll
    for (int i = 0; i < 2; ++i) {
        hi0[i] = __ldg(srcHi[i]);
        hi1[i] = __ldg(srcHi[i] + 32);
        sb0[i] = __ldg(srcSub[i]);
        sb1[i] = __ldg(srcSub[i] + 32);
    }

    // Phase 3: combine + store
#pragma unroll
    for (int i = 0; i < 2; ++i) {
        const float inv = 1.0f / fmaxf((float)(mv[i] + 1), 1e-13f);
        const float fs  = subScale[i] * inv;
        float4 r0, r1;
        r0.x = hi0[i].x * inv - sb0[i].x * fs;
        r0.y = hi0[i].y * inv - sb0[i].y * fs;
        r0.z = hi0[i].z * inv - sb0[i].z * fs;
        r0.w = hi0[i].w * inv - sb0[i].w * fs;
        r1.x = hi1[i].x * inv - sb1[i].x * fs;
        r1.y = hi1[i].y * inv - sb1[i].y * fs;
        r1.z = hi1[i].z * inv - sb1[i].z * fs;
        r1.w = hi1[i].w * inv - sb1[i].w * fs;

        float4* __restrict__ o = out4 + (size_t)(span0 + i) * SLOTS + lane;
        o[0]  = r0;
        o[32] = r1;
    }
}

extern "C" void kernel_launch(void* const* d_in, const int* in_sizes, int n_in,
                              void* d_out, int out_size)
{
    const float4* seq4  = (const float4*)d_in[0];  // sequence_tensor [B,S,D] f32
    const int2*   spans = (const int2*)  d_in[1];  // span_indices    [B,N,2] i32
    float4*       out4  = (float4*)d_out;          // [B,N,D] f32

    k_prep <<<(B_ * NBLK * SLOTS) / 128, 128>>>(seq4);
    k_spans<<<(B_ * N_) / 16, 256>>>(spans, out4);
}

// round 7
// speedup vs baseline: 1.5719x; 1.5719x over previous
#include <cuda_runtime.h>
#include <cstdint>

#define B_     8
#define S_     2048
#define N_     4096
#define D_     256
#define SLOTS  (D_ / 4)      // 64 float4 per row
#define BLK    16            // block >= max span extent (width <= 15 -> <= 16 rows)
#define NBLK   (S_ / BLK)    // 128

// Scratch (fp32): block-local inclusive prefix P, and U = P - blockTotal.
// Any span = exactly 2 row reads:
//   sum[low..end] = P[end] - (haveSub ? (cross ? U[low-1] : P[low-1]) : 0)
// (cross => haveSub, since a block-aligned crossing span would need >16 rows.)
__device__ float g_P[(size_t)B_ * S_ * D_];   // 16.8 MB
__device__ float g_U[(size_t)B_ * S_ * D_];   // 16.8 MB

// ── K1: block-local prefix + suffix, fully register-resident ────────────────
// thread = (b, blk, slot); 65536 threads, 512 CTAs of 128.
__global__ __launch_bounds__(128) void k_prep(const float4* __restrict__ seq4)
{
    const int tid  = blockIdx.x * 128 + threadIdx.x;
    const int slot = tid & (SLOTS - 1);
    const int p    = tid >> 6;                  // (b, blk)
    const int blk  = p & (NBLK - 1);
    const int b    = p >> 7;                    // NBLK = 128

    const size_t base = ((size_t)b * S_ + (size_t)blk * BLK) * SLOTS + slot;
    const float4* __restrict__ q = seq4 + base;

    // Load all 16 rows (MLP = 16), then prefix in registers.
    float4 v[BLK];
#pragma unroll
    for (int r = 0; r < BLK; ++r) v[r] = __ldg(q + r * SLOTS);
#pragma unroll
    for (int r = 1; r < BLK; ++r) {
        v[r].x += v[r - 1].x; v[r].y += v[r - 1].y;
        v[r].z += v[r - 1].z; v[r].w += v[r - 1].w;
    }
    const float4 tot = v[BLK - 1];

    float4* __restrict__ Pp = reinterpret_cast<float4*>(g_P) + base;
    float4* __restrict__ Up = reinterpret_cast<float4*>(g_U) + base;
#pragma unroll
    for (int r = 0; r < BLK; ++r) Pp[r * SLOTS] = v[r];
#pragma unroll
    for (int r = 0; r < BLK; ++r)
        Up[r * SLOTS] = make_float4(v[r].x - tot.x, v[r].y - tot.y,
                                    v[r].z - tot.z, v[r].w - tot.w);
}

// ── K2: spans — one warp per span, 4 unconditional loads, zero divergence ────
// blockDim 256 -> 8 spans per block, grid = 4096. (R4's proven-best shape.)
__global__ __launch_bounds__(256) void k_spans(
    const int2* __restrict__ spans,     // [B, N]
    float4*     __restrict__ out4)      // [B, N, D/4]
{
    const int span = blockIdx.x * 8 + (threadIdx.x >> 5);
    const int lane = threadIdx.x & 31;
    const int b    = span >> 12;                 // N_ = 4096

    const int2 se  = __ldg(&spans[span]);
    const int end  = se.y;
    const int m    = min(end - se.x, end);       // mask(w) <=> w <= m
    const int low  = end - m;                    // rows [low, end], count m+1

    const bool haveSub = (low & (BLK - 1)) != 0;
    const bool cross   = (low >> 4) != (end >> 4);
    const int  selRow  = max(low - 1, 0);

    const size_t bb = (size_t)b * S_ * SLOTS;
    const float4* __restrict__ hiP =
        reinterpret_cast<const float4*>(g_P) + bb + (size_t)end * SLOTS + lane;
    const float4* __restrict__ sbP =
        reinterpret_cast<const float4*>(cross ? g_U : g_P)
        + bb + (size_t)selRow * SLOTS + lane;

    // All four loads unconditional -> maximum MLP, no divergence.
    const float4 hi0 = __ldg(hiP);
    const float4 hi1 = __ldg(hiP + 32);
    const float4 sb0 = __ldg(sbP);
    const float4 sb1 = __ldg(sbP + 32);

    const float inv = 1.0f / fmaxf((float)(m + 1), 1e-13f);
    const float fs  = haveSub ? inv : 0.0f;

    float4 r0, r1;
    r0.x = hi0.x * inv - sb0.x * fs;  r0.y = hi0.y * inv - sb0.y * fs;
    r0.z = hi0.z * inv - sb0.z * fs;  r0.w = hi0.w * inv - sb0.w * fs;
    r1.x = hi1.x * inv - sb1.x * fs;  r1.y = hi1.y * inv - sb1.y * fs;
    r1.z = hi1.z * inv - sb1.z * fs;  r1.w = hi1.w * inv - sb1.w * fs;

    float4* __restrict__ o = out4 + (size_t)span * SLOTS + lane;
    o[0]  = r0;
    o[32] = r1;
}

extern "C" void kernel_launch(void* const* d_in, const int* in_sizes, int n_in,
                              void* d_out, int out_size)
{
    const float4* seq4  = (const float4*)d_in[0];  // sequence_tensor [B,S,D] f32
    const int2*   spans = (const int2*)  d_in[1];  // span_indices    [B,N,2] i32
    float4*       out4  = (float4*)d_out;          // [B,N,D] f32

    k_prep <<<(B_ * NBLK * SLOTS) / 128, 128>>>(seq4);
    k_spans<<<(B_ * N_) / 8, 256>>>(spans, out4);
}

// round 8
// speedup vs baseline: 1.7364x; 1.1047x over previous
#include <cuda_runtime.h>
#include <cstdint>

#define B_     8
#define S_     2048
#define N_     4096
#define D_     256
#define SLOTS  (D_ / 4)      // 64 float4 per row
#define BLK    16            // block >= max span extent (width <= 15 -> <= 16 rows)
#define NBLK   (S_ / BLK)    // 128

// Scratch (fp32): block-local inclusive prefix P (16.8 MB) + block totals T (1 MB).
// Span sum over rows [low, end]:
//   sum = P[end] + (cross ? T[blkE-1] : 0) - (haveSub ? P[low-1] : 0)
// where cross = blk(low) != blk(end), haveSub = (low & 15) != 0; cross => haveSub.
__device__ float g_P[(size_t)B_ * S_ * D_];            // 16.8 MB
__device__ float g_T[(size_t)B_ * NBLK * D_];          // 1 MB (hot in L2/L1)

// ── K1: block-local prefix + total, fully register-resident, one pass ────────
// thread = (b, blk, slot); 65536 threads, 512 CTAs of 128.
__global__ __launch_bounds__(128) void k_prep(const float4* __restrict__ seq4)
{
    const int tid  = blockIdx.x * 128 + threadIdx.x;
    const int slot = tid & (SLOTS - 1);
    const int p    = tid >> 6;                  // (b, blk)
    const int blk  = p & (NBLK - 1);
    const int b    = p >> 7;                    // NBLK = 128

    const size_t base = ((size_t)b * S_ + (size_t)blk * BLK) * SLOTS + slot;
    const float4* __restrict__ q = seq4 + base;

    float4 v[BLK];
#pragma unroll
    for (int r = 0; r < BLK; ++r) v[r] = __ldg(q + r * SLOTS);   // MLP = 16
#pragma unroll
    for (int r = 1; r < BLK; ++r) {
        v[r].x += v[r - 1].x; v[r].y += v[r - 1].y;
        v[r].z += v[r - 1].z; v[r].w += v[r - 1].w;
    }

    float4* __restrict__ Pp = reinterpret_cast<float4*>(g_P) + base;
#pragma unroll
    for (int r = 0; r < BLK; ++r) Pp[r * SLOTS] = v[r];

    reinterpret_cast<float4*>(g_T)[((size_t)b * NBLK + blk) * SLOTS + slot] = v[BLK - 1];
}

// ── K2: spans — one warp per span, 6 unconditional loads, zero divergence ────
// blockDim 256 -> 8 spans per block, grid = 4096.
__global__ __launch_bounds__(256) void k_spans(
    const int2* __restrict__ spans,     // [B, N]
    float4*     __restrict__ out4)      // [B, N, D/4]
{
    const int span = blockIdx.x * 8 + (threadIdx.x >> 5);
    const int lane = threadIdx.x & 31;
    const int b    = span >> 12;                 // N_ = 4096

    const int2 se  = __ldg(&spans[span]);
    const int end  = se.y;
    const int m    = min(end - se.x, end);       // mask(w) <=> w <= m
    const int low  = end - m;                    // rows [low, end], count m+1

    const bool haveSub = (low & (BLK - 1)) != 0;
    const bool cross   = (low >> 4) != (end >> 4);
    const int  selRow  = max(low - 1, 0);
    const int  selBlk  = max((end >> 4) - 1, 0);

    const float4* __restrict__ P4 = reinterpret_cast<const float4*>(g_P)
                                  + (size_t)b * S_ * SLOTS;
    const float4* __restrict__ hiP = P4 + (size_t)end    * SLOTS + lane;
    const float4* __restrict__ sbP = P4 + (size_t)selRow * SLOTS + lane;
    const float4* __restrict__ tP  = reinterpret_cast<const float4*>(g_T)
                                   + ((size_t)b * NBLK + selBlk) * SLOTS + lane;

    // All six loads unconditional -> max MLP, no divergence. T loads are hot (1 MB).
    const float4 hi0 = __ldg(hiP);
    const float4 hi1 = __ldg(hiP + 32);
    const float4 sb0 = __ldg(sbP);
    const float4 sb1 = __ldg(sbP + 32);
    const float4 t0  = __ldg(tP);
    const float4 t1  = __ldg(tP + 32);

    const float inv = 1.0f / fmaxf((float)(m + 1), 1e-13f);
    const float ft  = cross   ? inv : 0.0f;
    const float fs  = haveSub ? inv : 0.0f;

    float4 r0, r1;
    r0.x = hi0.x * inv + t0.x * ft - sb0.x * fs;
    r0.y = hi0.y * inv + t0.y * ft - sb0.y * fs;
    r0.z = hi0.z * inv + t0.z * ft - sb0.z * fs;
    r0.w = hi0.w * inv + t0.w * ft - sb0.w * fs;
    r1.x = hi1.x * inv + t1.x * ft - sb1.x * fs;
    r1.y = hi1.y * inv + t1.y * ft - sb1.y * fs;
    r1.z = hi1.z * inv + t1.z * ft - sb1.z * fs;
    r1.w = hi1.w * inv + t1.w * ft - sb1.w * fs;

    float4* __restrict__ o = out4 + (size_t)span * SLOTS + lane;
    o[0]  = r0;
    o[32] = r1;
}

extern "C" void kernel_launch(void* const* d_in, const int* in_sizes, int n_in,
                              void* d_out, int out_size)
{
    const float4* seq4  = (const float4*)d_in[0];  // sequence_tensor [B,S,D] f32
    const int2*   spans = (const int2*)  d_in[1];  // span_indices    [B,N,2] i32
    float4*       out4  = (float4*)d_out;          // [B,N,D] f32

    k_prep <<<(B_ * NBLK * SLOTS) / 128, 128>>>(seq4);
    k_spans<<<(B_ * N_) / 8, 256>>>(spans, out4);
}

// round 9
// speedup vs baseline: 1.7595x; 1.0133x over previous
#include <cuda_runtime.h>
#include <cstdint>

#define B_     8
#define S_     2048
#define N_     4096
#define D_     256
#define SLOTS  (D_ / 4)      // 64 float4 per row
#define BLK    16            // block >= max span extent (width <= 15 -> <= 16 rows)
#define NBLK   (S_ / BLK)    // 128

// Scratch (fp32): block-local inclusive prefix P (16.8 MB) + block totals T (1 MB).
// Span sum over rows [low, end]:
//   sum = P[end] + (cross ? T[blkE-1] : 0) - (haveSub ? P[low-1] : 0)
// where cross = blk(low) != blk(end); cross => haveSub (width <= 15).
__device__ float g_P[(size_t)B_ * S_ * D_];            // 16.8 MB
__device__ float g_T[(size_t)B_ * NBLK * D_];          // 1 MB (hot in L2/L1)

// ── K1: block-local prefix + total, register-resident, single pass ───────────
// thread = (b, blk, slot); 65536 threads, 512 CTAs of 128.
__global__ __launch_bounds__(128) void k_prep(const float4* __restrict__ seq4)
{
    const int tid  = blockIdx.x * 128 + threadIdx.x;
    const int slot = tid & (SLOTS - 1);
    const int p    = tid >> 6;                  // (b, blk)
    const int blk  = p & (NBLK - 1);
    const int b    = p >> 7;                    // NBLK = 128

    const size_t base = ((size_t)b * S_ + (size_t)blk * BLK) * SLOTS + slot;
    const float4* __restrict__ q = seq4 + base;

    float4 v[BLK];
#pragma unroll
    for (int r = 0; r < BLK; ++r) v[r] = __ldg(q + r * SLOTS);   // MLP = 16
#pragma unroll
    for (int r = 1; r < BLK; ++r) {
        v[r].x += v[r - 1].x; v[r].y += v[r - 1].y;
        v[r].z += v[r - 1].z; v[r].w += v[r - 1].w;
    }

    float4* __restrict__ Pp = reinterpret_cast<float4*>(g_P) + base;
#pragma unroll
    for (int r = 0; r < BLK; ++r) Pp[r * SLOTS] = v[r];

    reinterpret_cast<float4*>(g_T)[((size_t)b * NBLK + blk) * SLOTS + slot] = v[BLK - 1];
}

// ── K2: spans — warp per span; hi+sub unconditional, T behind uniform branch ─
// blockDim 256 -> 8 spans per block, grid = 4096.
__global__ __launch_bounds__(256) void k_spans(
    const int2* __restrict__ spans,     // [B, N]
    float4*     __restrict__ out4)      // [B, N, D/4]
{
    const int span = blockIdx.x * 8 + (threadIdx.x >> 5);
    const int lane = threadIdx.x & 31;
    const int b    = span >> 12;                 // N_ = 4096

    const int2 se  = __ldg(&spans[span]);
    const int end  = se.y;
    const int m    = min(end - se.x, end);       // mask(w) <=> w <= m
    const int low  = end - m;                    // rows [low, end], count m+1

    const bool haveSub = (low & (BLK - 1)) != 0;
    const bool cross   = (low >> 4) != (end >> 4);   // cross => haveSub, blkE >= 1
    const int  selRow  = max(low - 1, 0);

    const float4* __restrict__ P4 = reinterpret_cast<const float4*>(g_P)
                                  + (size_t)b * S_ * SLOTS;
    const float4* __restrict__ hiP = P4 + (size_t)end    * SLOTS + lane;
    const float4* __restrict__ sbP = P4 + (size_t)selRow * SLOTS + lane;

    // Four unconditional loads (deep MLP).
    const float4 hi0 = __ldg(hiP);
    const float4 hi1 = __ldg(hiP + 32);
    const float4 sb0 = __ldg(sbP);
    const float4 sb1 = __ldg(sbP + 32);

    const float inv = 1.0f / fmaxf((float)(m + 1), 1e-13f);
    const float fs  = haveSub ? inv : 0.0f;

    float4 r0, r1;
    r0.x = hi0.x * inv - sb0.x * fs;  r0.y = hi0.y * inv - sb0.y * fs;
    r0.z = hi0.z * inv - sb0.z * fs;  r0.w = hi0.w * inv - sb0.w * fs;
    r1.x = hi1.x * inv - sb1.x * fs;  r1.y = hi1.y * inv - sb1.y * fs;
    r1.z = hi1.z * inv - sb1.z * fs;  r1.w = hi1.w * inv - sb1.w * fs;

    if (cross) {   // warp-uniform; ~47% of spans. T rows hot in L1/L2 (1 MB table).
        const float4* __restrict__ tP = reinterpret_cast<const float4*>(g_T)
            + ((size_t)b * NBLK + ((end >> 4) - 1)) * SLOTS + lane;
        const float4 t0 = __ldg(tP);
        const float4 t1 = __ldg(tP + 32);
        r0.x += t0.x * inv;  r0.y += t0.y * inv;
        r0.z += t0.z * inv;  r0.w += t0.w * inv;
        r1.x += t1.x * inv;  r1.y += t1.y * inv;
        r1.z += t1.z * inv;  r1.w += t1.w * inv;
    }

    float4* __restrict__ o = out4 + (size_t)span * SLOTS + lane;
    o[0]  = r0;
    o[32] = r1;
}

extern "C" void kernel_launch(void* const* d_in, const int* in_sizes, int n_in,
                              void* d_out, int out_size)
{
    const float4* seq4  = (const float4*)d_in[0];  // sequence_tensor [B,S,D] f32
    const int2*   spans = (const int2*)  d_in[1];  // span_indices    [B,N,2] i32
    float4*       out4  = (float4*)d_out;          // [B,N,D] f32

    k_prep <<<(B_ * NBLK * SLOTS) / 128, 128>>>(seq4);
    k_spans<<<(B_ * N_) / 8, 256>>>(spans, out4);
}

// round 10
// speedup vs baseline: 1.7628x; 1.0019x over previous
#include <cuda_runtime.h>
#include <cstdint>

#define B_     8
#define S_     2048
#define N_     4096
#define D_     256
#define SLOTS  (D_ / 4)      // 64 float4 per row
#define BLK    16            // block >= max span extent (width <= 15 -> <= 16 rows)
#define NBLK   (S_ / BLK)    // 128

// Scratch (fp32): block-local inclusive prefix P (16.8 MB) + block totals T (1 MB).
// Span sum over rows [low, end]:
//   sum = P[end] + (cross ? T[blkE-1] : 0) - (haveSub ? P[low-1] : 0)
// cross = blk(low) != blk(end); cross => haveSub (width <= 15).
__device__ float g_P[(size_t)B_ * S_ * D_];            // 16.8 MB
__device__ float g_T[(size_t)B_ * NBLK * D_];          // 1 MB (hot in L2/L1)

// ── K1: streaming block-local prefix + total (R5's measured-fastest shape) ───
// thread = (b, blk, slot); 65536 threads, 512 CTAs of 128. Low regs, high occ.
__global__ __launch_bounds__(128) void k_prep(const float4* __restrict__ seq4)
{
    const int tid  = blockIdx.x * 128 + threadIdx.x;
    const int slot = tid & (SLOTS - 1);
    const int p    = tid >> 6;                  // (b, blk)
    const int blk  = p & (NBLK - 1);
    const int b    = p >> 7;                    // NBLK = 128

    const size_t base = ((size_t)b * S_ + (size_t)blk * BLK) * SLOTS + slot;
    const float4* __restrict__ q  = seq4 + base;
    float4* __restrict__        Pp = reinterpret_cast<float4*>(g_P) + base;

    float4 s = make_float4(0.f, 0.f, 0.f, 0.f);
#pragma unroll
    for (int r = 0; r < BLK; ++r) {
        const float4 v = __ldg(q + r * SLOTS);   // loads independent -> batched
        s.x += v.x; s.y += v.y; s.z += v.z; s.w += v.w;
        Pp[r * SLOTS] = s;                       // streaming store, no array
    }
    reinterpret_cast<float4*>(g_T)[((size_t)b * NBLK + blk) * SLOTS + slot] = s;
}

// ── K2: spans — 64 threads per span (1 float4 each), minimal regs, max TLP ───
// blockDim 256 -> 4 spans per block, grid = 8192. `cross` uniform per warp.
__global__ __launch_bounds__(256) void k_spans(
    const int2* __restrict__ spans,     // [B, N]
    float4*     __restrict__ out4)      // [B, N, D/4]
{
    const int span = blockIdx.x * 4 + (threadIdx.x >> 6);
    const int g    = threadIdx.x & 63;           // float4 slot within D
    const int b    = span >> 12;                 // N_ = 4096

    const int2 se  = __ldg(&spans[span]);
    const int end  = se.y;
    const int m    = min(end - se.x, end);       // mask(w) <=> w <= m
    const int low  = end - m;                    // rows [low, end], count m+1

    const bool haveSub = (low & (BLK - 1)) != 0;
    const bool cross   = (low >> 4) != (end >> 4);   // => haveSub, blkE >= 1
    const int  selRow  = max(low - 1, 0);

    const float4* __restrict__ P4 = reinterpret_cast<const float4*>(g_P)
                                  + (size_t)b * S_ * SLOTS;

    // Two unconditional loads (independent).
    const float4 hi = __ldg(P4 + (size_t)end    * SLOTS + g);
    const float4 sb = __ldg(P4 + (size_t)selRow * SLOTS + g);

    const float inv = 1.0f / fmaxf((float)(m + 1), 1e-13f);
    const float fs  = haveSub ? inv : 0.0f;

    float4 r;
    r.x = hi.x * inv - sb.x * fs;
    r.y = hi.y * inv - sb.y * fs;
    r.z = hi.z * inv - sb.z * fs;
    r.w = hi.w * inv - sb.w * fs;

    if (cross) {   // warp-uniform (one span per warp-group of 64 -> per warp too)
        const float4 t = __ldg(reinterpret_cast<const float4*>(g_T)
            + ((size_t)b * NBLK + ((end >> 4) - 1)) * SLOTS + g);
        r.x += t.x * inv;  r.y += t.y * inv;
        r.z += t.z * inv;  r.w += t.w * inv;
    }

    out4[(size_t)span * SLOTS + g] = r;
}

extern "C" void kernel_launch(void* const* d_in, const int* in_sizes, int n_in,
                              void* d_out, int out_size)
{
    const float4* seq4  = (const float4*)d_in[0];  // sequence_tensor [B,S,D] f32
    const int2*   spans = (const int2*)  d_in[1];  // span_indices    [B,N,2] i32
    float4*       out4  = (float4*)d_out;          // [B,N,D] f32

    k_prep <<<(B_ * NBLK * SLOTS) / 128, 128>>>(seq4);
    k_spans<<<(B_ * N_) / 4, 256>>>(spans, out4);
}